// round 3
// baseline (speedup 1.0000x reference)
#include <cuda_runtime.h>
#include <cuda_bf16.h>
#include <cstdint>

#define L_SEQ 8192
#define E_DIM 256
#define HDIM 256
#define G4 1024
#define T_TAGS 34
#define START_TAG 32
#define NEG_VAL -10000.0f

__device__ float g_x[L_SEQ * E_DIM];
__device__ float g_igf[L_SEQ * G4];
__device__ float g_igb[L_SEQ * G4];
__device__ float g_hf[L_SEQ * HDIM];
__device__ float g_hb[L_SEQ * HDIM];
__device__ float g_feats[L_SEQ * T_TAGS];
__device__ float g_la[L_SEQ * T_TAGS];
__device__ float g_lb[L_SEQ * T_TAGS];

__device__ __forceinline__ float neg_inf() { return __int_as_float(0xff800000); }
__device__ __forceinline__ float sigmoidf_(float x) { return __fdividef(1.f, 1.f + __expf(-x)); }
__device__ __forceinline__ float tanhf_(float x) {
    float ax = fabsf(x);
    float e = __expf(-2.f * ax);
    float r = __fdividef(1.f - e, 1.f + e);
    return x < 0.f ? -r : r;
}

// ------------- embedding gather -------------
__global__ void gather_kernel(const int* __restrict__ words, const float* __restrict__ embed) {
    int t = blockIdx.x;
    g_x[t * E_DIM + threadIdx.x] = embed[(long)words[t] * E_DIM + threadIdx.x];
}

// ------------- input projections: out[t][r] = x[t]·Wih[r] + b[r] -------------
__global__ void igates_kernel(const float* __restrict__ Wih_f, const float* __restrict__ b_f,
                              const float* __restrict__ Wih_b, const float* __restrict__ b_b) {
    const float* W = blockIdx.z ? Wih_b : Wih_f;
    const float* b = blockIdx.z ? b_b : b_f;
    float* out = blockIdx.z ? g_igb : g_igf;
    __shared__ float ws[128][65];
    __shared__ __align__(16) float xsT[64][20];
    int tid = threadIdx.x;
    int t0 = blockIdx.x * 16, r0 = blockIdx.y * 128;
    float acc[16];
#pragma unroll
    for (int i = 0; i < 16; i++) acc[i] = 0.f;
    for (int kc = 0; kc < 4; kc++) {
        int kb = kc * 64;
        for (int i = tid; i < 1024; i += 128)
            xsT[i & 63][i >> 6] = g_x[(t0 + (i >> 6)) * E_DIM + kb + (i & 63)];
        for (int i = tid; i < 8192; i += 128)
            ws[i >> 6][i & 63] = W[(r0 + (i >> 6)) * E_DIM + kb + (i & 63)];
        __syncthreads();
#pragma unroll 8
        for (int k = 0; k < 64; k++) {
            float wv = ws[tid][k];
            float4 x0 = *(const float4*)&xsT[k][0];
            float4 x1 = *(const float4*)&xsT[k][4];
            float4 x2 = *(const float4*)&xsT[k][8];
            float4 x3 = *(const float4*)&xsT[k][12];
            acc[0] = fmaf(wv, x0.x, acc[0]);   acc[1] = fmaf(wv, x0.y, acc[1]);
            acc[2] = fmaf(wv, x0.z, acc[2]);   acc[3] = fmaf(wv, x0.w, acc[3]);
            acc[4] = fmaf(wv, x1.x, acc[4]);   acc[5] = fmaf(wv, x1.y, acc[5]);
            acc[6] = fmaf(wv, x1.z, acc[6]);   acc[7] = fmaf(wv, x1.w, acc[7]);
            acc[8] = fmaf(wv, x2.x, acc[8]);   acc[9] = fmaf(wv, x2.y, acc[9]);
            acc[10] = fmaf(wv, x2.z, acc[10]); acc[11] = fmaf(wv, x2.w, acc[11]);
            acc[12] = fmaf(wv, x3.x, acc[12]); acc[13] = fmaf(wv, x3.y, acc[13]);
            acc[14] = fmaf(wv, x3.z, acc[14]); acc[15] = fmaf(wv, x3.w, acc[15]);
        }
        __syncthreads();
    }
    float bias = b[r0 + tid];
#pragma unroll
    for (int tt = 0; tt < 16; tt++)
        out[(t0 + tt) * G4 + r0 + tid] = acc[tt] + bias;
}

// ------------- cluster-parallel persistent BiLSTM -------------
// 2 clusters of 8 CTAs x 512 threads. CTA rank owns hidden units [32r,32r+32),
// i.e. gate rows {g*256+unit}. Whh slice in registers. h replicated per-CTA in
// SMEM (double buffered), refreshed via st.shared::cluster + cluster barrier.
__global__ void __cluster_dims__(8, 1, 1) __launch_bounds__(512, 1)
lstm_kernel(const float* __restrict__ Whh_f, const float* __restrict__ Whh_b) {
    __shared__ __align__(16) float hsm[2][HDIM];
    __shared__ float part[512];
    __shared__ float igsm[128];
    int tid = threadIdx.x;
    int dir = blockIdx.x >> 3;
    unsigned rank;
    asm("mov.u32 %0, %%cluster_ctarank;" : "=r"(rank));
    const float* Whh = dir ? Whh_b : Whh_f;
    const float* ig = dir ? g_igb : g_igf;
    float* hout = dir ? g_hb : g_hf;

    int row_local = tid & 127;
    int kseg = tid >> 7;
    int kb = kseg * 64;
    int g = row_local >> 5;
    int u = row_local & 31;
    int unit = (int)rank * 32 + u;
    int grow = g * 256 + unit;

    float w[64];
#pragma unroll
    for (int i = 0; i < 64; i++) w[i] = Whh[grow * 256 + kb + i];

    hsm[tid >> 8][tid & 255] = 0.f;
    float c_state = 0.f;
    int pos0 = dir ? (L_SEQ - 1) : 0;
    float ig_cur = (tid < 128) ? ig[pos0 * G4 + grow] : 0.f;

    asm volatile("barrier.cluster.arrive.aligned;" ::: "memory");
    asm volatile("barrier.cluster.wait.aligned;" ::: "memory");

    for (int t = 0; t < L_SEQ; t++) {
        int posn = dir ? (L_SEQ - 2 - t) : (t + 1);
        float ig_nxt = (tid < 128 && t + 1 < L_SEQ) ? ig[posn * G4 + grow] : 0.f;
        if (tid < 128) igsm[row_local] = ig_cur;

        const float* hprev = hsm[t & 1];
        float a0 = 0.f, a1 = 0.f;
#pragma unroll
        for (int i = 0; i < 64; i += 4) {
            float4 hv = *(const float4*)&hprev[kb + i];
            a0 = fmaf(w[i + 0], hv.x, a0);
            a1 = fmaf(w[i + 1], hv.y, a1);
            a0 = fmaf(w[i + 2], hv.z, a0);
            a1 = fmaf(w[i + 3], hv.w, a1);
        }
        part[kseg * 128 + row_local] = a0 + a1;
        __syncthreads();

        if (tid < 32) {
            float zi = igsm[tid]      + part[tid]      + part[128 + tid] + part[256 + tid] + part[384 + tid];
            float zf = igsm[32 + tid] + part[32 + tid] + part[160 + tid] + part[288 + tid] + part[416 + tid];
            float zg = igsm[64 + tid] + part[64 + tid] + part[192 + tid] + part[320 + tid] + part[448 + tid];
            float zo = igsm[96 + tid] + part[96 + tid] + part[224 + tid] + part[352 + tid] + part[480 + tid];
            float gi = sigmoidf_(zi), gf = sigmoidf_(zf);
            float gg = tanhf_(zg), go = sigmoidf_(zo);
            c_state = fmaf(gf, c_state, gi * gg);
            float h = go * tanhf_(c_state);
            int pos = dir ? (L_SEQ - 1 - t) : t;
            hout[pos * HDIM + (int)rank * 32 + tid] = h;
            unsigned laddr = (unsigned)__cvta_generic_to_shared(&hsm[(t & 1) ^ 1][(int)rank * 32 + tid]);
#pragma unroll
            for (int r = 0; r < 8; r++) {
                unsigned raddr;
                asm("mapa.shared::cluster.u32 %0, %1, %2;" : "=r"(raddr) : "r"(laddr), "r"(r));
                asm volatile("st.shared::cluster.f32 [%0], %1;" :: "r"(raddr), "f"(h));
            }
        }
        ig_cur = ig_nxt;
        asm volatile("barrier.cluster.arrive.aligned;" ::: "memory");
        asm volatile("barrier.cluster.wait.aligned;" ::: "memory");
    }
}

// ------------- feats = [hf|hb] @ W_out^T + b_out -------------
__global__ void feats_kernel(const float* __restrict__ W_out, const float* __restrict__ b_out) {
    __shared__ float ws[T_TAGS][257];
    int tid = threadIdx.x;
    int tk = tid / 34, j = tid % 34;
    int t = blockIdx.x * 8 + tk;
    bool act = tid < 272;
    float acc = act ? b_out[j] : 0.f;
    for (int half = 0; half < 2; half++) {
        for (int i = tid; i < T_TAGS * 256; i += 288)
            ws[i >> 8][i & 255] = W_out[(i >> 8) * 512 + half * 256 + (i & 255)];
        __syncthreads();
        if (act) {
            const float* h = half ? &g_hb[t * HDIM] : &g_hf[t * HDIM];
#pragma unroll 4
            for (int k = 0; k < 256; k++) acc = fmaf(h[k], ws[j][k], acc);
        }
        __syncthreads();
    }
    if (act) g_feats[t * T_TAGS + j] = acc;
}

// ------------- CRF forward (block 0) and backward (block 1) scans -------------
__global__ void crf_kernel(const float* __restrict__ trans) {
    __shared__ float buf[40];
    __shared__ float qbuf[40];
    __shared__ float pmax[2][40];
    __shared__ float psum[2][40];
    int tid = threadIdx.x;
    int j = tid % 34;
    int s = tid / 34;
    bool act = tid < 68;

    if (blockIdx.x == 0) {
        // alpha_t[j] = lse_i(alpha[i] + trans[j][i]) + feat_t[j]
        float tr[17];
        if (act) {
#pragma unroll
            for (int m = 0; m < 17; m++) tr[m] = trans[j * T_TAGS + s + 2 * m];
        }
        if (tid < 34) buf[tid] = (tid == START_TAG) ? 0.f : NEG_VAL;
        __syncthreads();
        for (int t = 0; t < L_SEQ; t++) {
            if (act) {
                float m0 = neg_inf();
#pragma unroll
                for (int m = 0; m < 17; m++) m0 = fmaxf(m0, buf[s + 2 * m] + tr[m]);
                pmax[s][j] = m0;
            }
            __syncthreads();
            if (act) {
                float M = fmaxf(pmax[0][j], pmax[1][j]);
                float ss = 0.f;
#pragma unroll
                for (int m = 0; m < 17; m++) ss += __expf(buf[s + 2 * m] + tr[m] - M);
                psum[s][j] = ss;
            }
            __syncthreads();
            if (tid < 34) {
                float M = fmaxf(pmax[0][tid], pmax[1][tid]);
                float v = M + __logf(psum[0][tid] + psum[1][tid]) + g_feats[t * T_TAGS + tid];
                g_la[t * T_TAGS + tid] = v;
                buf[tid] = v;
            }
            __syncthreads();
        }
    } else {
        // beta_t[j] = lse_i(beta_{t+1}[i] + feat_{t+1}[i] + trans[i][j])
        float tr[17];
        if (act) {
#pragma unroll
            for (int m = 0; m < 17; m++) tr[m] = trans[(s + 2 * m) * T_TAGS + j];
        }
        // beta_last[j] = lse_i(trans[i][j])
        if (act) {
            float m0 = neg_inf();
#pragma unroll
            for (int m = 0; m < 17; m++) m0 = fmaxf(m0, tr[m]);
            pmax[s][j] = m0;
        }
        __syncthreads();
        if (act) {
            float M = fmaxf(pmax[0][j], pmax[1][j]);
            float ss = 0.f;
#pragma unroll
            for (int m = 0; m < 17; m++) ss += __expf(tr[m] - M);
            psum[s][j] = ss;
        }
        __syncthreads();
        if (tid < 34) {
            float M = fmaxf(pmax[0][tid], pmax[1][tid]);
            float v = M + __logf(psum[0][tid] + psum[1][tid]);
            g_lb[(L_SEQ - 1) * T_TAGS + tid] = v;
            buf[tid] = v;
        }
        __syncthreads();
        for (int t = L_SEQ - 2; t >= 0; t--) {
            if (tid < 34) qbuf[tid] = buf[tid] + g_feats[(t + 1) * T_TAGS + tid];
            __syncthreads();
            if (act) {
                float m0 = neg_inf();
#pragma unroll
                for (int m = 0; m < 17; m++) m0 = fmaxf(m0, qbuf[s + 2 * m] + tr[m]);
                pmax[s][j] = m0;
            }
            __syncthreads();
            if (act) {
                float M = fmaxf(pmax[0][j], pmax[1][j]);
                float ss = 0.f;
#pragma unroll
                for (int m = 0; m < 17; m++) ss += __expf(qbuf[s + 2 * m] + tr[m] - M);
                psum[s][j] = ss;
            }
            __syncthreads();
            if (tid < 34) {
                float M = fmaxf(pmax[0][tid], pmax[1][tid]);
                float v = M + __logf(psum[0][tid] + psum[1][tid]);
                g_lb[t * T_TAGS + tid] = v;
                buf[tid] = v;
            }
            __syncthreads();
        }
    }
}

// ------------- score = la + lb, tags = argmax -------------
__global__ void finalize_kernel(float* out, int out_size) {
    int t = blockIdx.x * blockDim.x + threadIdx.x;
    if (t >= L_SEQ) return;
    bool has_score = out_size >= L_SEQ * T_TAGS;
    float best = neg_inf();
    int bj = 0;
#pragma unroll 2
    for (int jj = 0; jj < T_TAGS; jj++) {
        float v = g_la[t * T_TAGS + jj] + g_lb[t * T_TAGS + jj];
        if (has_score) out[t * T_TAGS + jj] = v;
        if (v > best) { best = v; bj = jj; }
    }
    if (out_size >= L_SEQ * T_TAGS + L_SEQ) out[L_SEQ * T_TAGS + t] = (float)bj;
    else if (out_size == L_SEQ) ((int*)out)[t] = bj;
}

extern "C" void kernel_launch(void* const* d_in, const int* in_sizes, int n_in,
                              void* d_out, int out_size) {
    const int* words   = (const int*)d_in[0];
    const float* embed = (const float*)d_in[1];
    const float* Wih_f = (const float*)d_in[2];
    const float* Whh_f = (const float*)d_in[3];
    const float* b_f   = (const float*)d_in[4];
    const float* Wih_b = (const float*)d_in[5];
    const float* Whh_b = (const float*)d_in[6];
    const float* b_b   = (const float*)d_in[7];
    const float* W_out = (const float*)d_in[8];
    const float* b_out = (const float*)d_in[9];
    const float* trans = (const float*)d_in[10];

    gather_kernel<<<L_SEQ, E_DIM>>>(words, embed);
    dim3 ig_grid(L_SEQ / 16, 8, 2);
    igates_kernel<<<ig_grid, 128>>>(Wih_f, b_f, Wih_b, b_b);
    lstm_kernel<<<16, 512>>>(Whh_f, Whh_b);
    feats_kernel<<<L_SEQ / 8, 288>>>(W_out, b_out);
    crf_kernel<<<2, 96>>>(trans);
    finalize_kernel<<<(L_SEQ + 127) / 128, 128>>>((float*)d_out, out_size);
}